// round 6
// baseline (speedup 1.0000x reference)
#include <cuda_runtime.h>
#include <cuda_bf16.h>
#include <math.h>

#define Hdim 1024
#define Ldim 10
#define Vdim 50257
#define ROWS_PER_BLK 32
#define NB5 ((Vdim + ROWS_PER_BLK - 1) / ROWS_PER_BLK)    // 1571
#define NB7 ((Vdim + 255) / 256)                          // 197

// ---- scratch (no allocations allowed) ----
__device__ __align__(16) float g_xcat[2 * Hdim];
__device__ __align__(16) float g_x[Hdim];
__device__ __align__(16) float g_gh[3 * Hdim];     // whh@h + bhh (r,z,n parts)
__device__ __align__(16) float g_hnew[Hdim];
__device__ __align__(16) float g_logits[Vdim];
__device__ float g_pmax[NB5];
__device__ float g_psum[NB5];

__device__ __forceinline__ float warp_sum(float s) {
#pragma unroll
    for (int o = 16; o; o >>= 1) s += __shfl_down_sync(0xffffffffu, s, o);
    return s;
}

__device__ __forceinline__ void lse_merge(float& m, float& s, float m2, float s2) {
    if (m2 > m) { s = s * expf(m - m2) + s2; m = m2; }
    else if (s2 > 0.f) { s += s2 * expf(m2 - m); }
}

// K0: gh = whh @ h + bhh. Independent of everything else -> runs first, no gridsync.
// Block per hidden unit, 256 threads, 3 rows.
__global__ __launch_bounds__(256) void k0_gruh(const float* __restrict__ hidden,
                                               const float* __restrict__ whh,
                                               const float* __restrict__ bhh) {
    cudaTriggerProgrammaticLaunchCompletion();
    __shared__ float red[3][8];
    int u = blockIdx.x;
    int tid = threadIdx.x, warp = tid >> 5, lane = tid & 31;
    const float4* whr = (const float4*)(whh + (size_t)u * Hdim);
    const float4* whz = (const float4*)(whh + (size_t)(u + Hdim) * Hdim);
    const float4* whn = (const float4*)(whh + (size_t)(u + 2 * Hdim) * Hdim);
    float4 hv = ((const float4*)hidden)[tid];
    float4 a;
    a = __ldcs(whr + tid); float s0 = a.x * hv.x + a.y * hv.y + a.z * hv.z + a.w * hv.w;
    a = __ldcs(whz + tid); float s1 = a.x * hv.x + a.y * hv.y + a.z * hv.z + a.w * hv.w;
    a = __ldcs(whn + tid); float s2 = a.x * hv.x + a.y * hv.y + a.z * hv.z + a.w * hv.w;
    s0 = warp_sum(s0); s1 = warp_sum(s1); s2 = warp_sum(s2);
    if (lane == 0) { red[0][warp] = s0; red[1][warp] = s1; red[2][warp] = s2; }
    __syncthreads();
    if (tid < 3) {
        float acc = 0.f;
#pragma unroll
        for (int w = 0; w < 8; w++) acc += red[tid][w];
        g_gh[tid * Hdim + u] = acc + bhh[tid * Hdim + u];
    }
}

// K1: embedding gather + attention scores + softmax + attn_applied -> g_xcat
// Reads only harness inputs -> no gridsync.
__global__ void k1_attn(const int* __restrict__ inp,
                        const float* __restrict__ hidden,
                        const float* __restrict__ enc,
                        const float* __restrict__ emb,
                        const float* __restrict__ attn_W,
                        const float* __restrict__ attn_b,
                        float* __restrict__ out, int out_size) {
    cudaTriggerProgrammaticLaunchCompletion();
    __shared__ float sw[Ldim];
    int tid = threadIdx.x;
    int warp = tid >> 5, lane = tid & 31;
    int tok = inp[0];
    const float* erow = emb + (size_t)tok * Hdim;

    if (warp < Ldim) {
        const float* wrow = attn_W + (size_t)warp * 2 * Hdim;
        float s = 0.f;
        for (int j = lane; j < Hdim; j += 32)
            s += wrow[j] * erow[j] + wrow[Hdim + j] * hidden[j];
        s = warp_sum(s);
        if (lane == 0) sw[warp] = s + attn_b[warp];
    }
    __syncthreads();
    if (tid == 0) {
        float m = sw[0];
#pragma unroll
        for (int l = 1; l < Ldim; l++) m = fmaxf(m, sw[l]);
        float e[Ldim], ssum = 0.f;
#pragma unroll
        for (int l = 0; l < Ldim; l++) { e[l] = expf(sw[l] - m); ssum += e[l]; }
#pragma unroll
        for (int l = 0; l < Ldim; l++) sw[l] = e[l] / ssum;
    }
    __syncthreads();
    if (tid < Ldim && out_size >= Vdim + Hdim + Ldim)
        out[Vdim + Hdim + tid] = sw[tid];
    int j = tid;
    if (j < Hdim) {
        float a = 0.f;
#pragma unroll
        for (int l = 0; l < Ldim; l++) a += sw[l] * enc[l * Hdim + j];
        g_xcat[j] = erow[j];
        g_xcat[Hdim + j] = a;
    }
}

// K2: g_x[row] = relu(comb_W[row,:] . g_xcat + b). Block per row, 512 threads.
__global__ __launch_bounds__(512) void k2_comb(const float* __restrict__ comb_W,
                                               const float* __restrict__ comb_b) {
    cudaTriggerProgrammaticLaunchCompletion();
    __shared__ float red[16];
    int row = blockIdx.x;
    int tid = threadIdx.x, warp = tid >> 5, lane = tid & 31;
    const float4* wr = (const float4*)(comb_W + (size_t)row * 2 * Hdim);
    float4 w = __ldcs(wr + tid);
    float bias = (tid == 0) ? comb_b[row] : 0.f;
    cudaGridDependencySynchronize();
    float4 x = ((const float4*)g_xcat)[tid];
    float s = w.x * x.x + w.y * x.y + w.z * x.z + w.w * x.w;
    s = warp_sum(s);
    if (lane == 0) red[warp] = s;
    __syncthreads();
    if (warp == 0) {
        float v = (lane < 16) ? red[lane] : 0.f;
        v = warp_sum(v);
        if (lane == 0) g_x[row] = fmaxf(v + bias, 0.f);
    }
}

// K3i: gi = wih @ x + bih; combine with g_gh -> h_new. Block per unit, 256 thr.
__global__ __launch_bounds__(256) void k3_grui(const float* __restrict__ hidden,
                                               const float* __restrict__ wih,
                                               const float* __restrict__ bih,
                                               float* __restrict__ out, int out_size) {
    cudaTriggerProgrammaticLaunchCompletion();
    __shared__ float red[3][8];
    int u = blockIdx.x;
    int tid = threadIdx.x, warp = tid >> 5, lane = tid & 31;
    const float4* wir = (const float4*)(wih + (size_t)u * Hdim);
    const float4* wiz = (const float4*)(wih + (size_t)(u + Hdim) * Hdim);
    const float4* win = (const float4*)(wih + (size_t)(u + 2 * Hdim) * Hdim);
    // weight loads independent of predecessors
    float4 a0 = __ldcs(wir + tid);
    float4 a1 = __ldcs(wiz + tid);
    float4 a2 = __ldcs(win + tid);
    cudaGridDependencySynchronize();
    float4 xv = ((const float4*)g_x)[tid];
    float s0 = a0.x * xv.x + a0.y * xv.y + a0.z * xv.z + a0.w * xv.w;
    float s1 = a1.x * xv.x + a1.y * xv.y + a1.z * xv.z + a1.w * xv.w;
    float s2 = a2.x * xv.x + a2.y * xv.y + a2.z * xv.z + a2.w * xv.w;
    s0 = warp_sum(s0); s1 = warp_sum(s1); s2 = warp_sum(s2);
    if (lane == 0) { red[0][warp] = s0; red[1][warp] = s1; red[2][warp] = s2; }
    __syncthreads();
    if (tid == 0) {
        float g0 = 0.f, g1 = 0.f, g2 = 0.f;
#pragma unroll
        for (int w = 0; w < 8; w++) { g0 += red[0][w]; g1 += red[1][w]; g2 += red[2][w]; }
        float r = 1.f / (1.f + expf(-((g0 + bih[u]) + g_gh[u])));
        float z = 1.f / (1.f + expf(-((g1 + bih[Hdim + u]) + g_gh[Hdim + u])));
        float n = tanhf((g2 + bih[2 * Hdim + u]) + r * g_gh[2 * Hdim + u]);
        float hn = (1.f - z) * n + z * hidden[u];
        g_hnew[u] = hn;
        if (out_size >= Vdim + Hdim) out[Vdim + u] = hn;
    }
}

// K5: logits + per-block (max, sumexp). 512 threads, 16 warps x 2 rows.
__global__ __launch_bounds__(512) void k5_logits(const float* __restrict__ outW,
                                                 const float* __restrict__ outb) {
    cudaTriggerProgrammaticLaunchCompletion();
    __shared__ __align__(16) float sh[Hdim];
    __shared__ float slog[ROWS_PER_BLK];
    int tid = threadIdx.x, warp = tid >> 5, lane = tid & 31;
    int row0 = blockIdx.x * ROWS_PER_BLK + warp * 2;
    int row1 = row0 + 1;
    bool v0 = row0 < Vdim, v1 = row1 < Vdim;
    const float4* wr0 = (const float4*)(outW + (size_t)(v0 ? row0 : 0) * Hdim);
    const float4* wr1 = (const float4*)(outW + (size_t)(v1 ? row1 : 0) * Hdim);
    float4 p0 = __ldcs(wr0 + lane);
    float4 p1 = __ldcs(wr1 + lane);
    cudaGridDependencySynchronize();
    sh[tid] = g_hnew[tid];
    sh[tid + 512] = g_hnew[tid + 512];
    __syncthreads();
    const float4* hh = (const float4*)sh;
    float4 h0 = hh[lane];
    float s0 = p0.x * h0.x + p0.y * h0.y + p0.z * h0.z + p0.w * h0.w;
    float s1 = p1.x * h0.x + p1.y * h0.y + p1.z * h0.z + p1.w * h0.w;
#pragma unroll
    for (int k = 1; k < 8; k++) {
        int idx = lane + 32 * k;
        float4 h = hh[idx];
        float4 w0 = __ldcs(wr0 + idx);
        float4 w1 = __ldcs(wr1 + idx);
        s0 += w0.x * h.x + w0.y * h.y + w0.z * h.z + w0.w * h.w;
        s1 += w1.x * h.x + w1.y * h.y + w1.z * h.z + w1.w * h.w;
    }
    s0 = warp_sum(s0);
    s1 = warp_sum(s1);
    if (lane == 0) {
        float lg0 = v0 ? (s0 + outb[row0]) : -INFINITY;
        float lg1 = v1 ? (s1 + outb[row1]) : -INFINITY;
        if (v0) g_logits[row0] = lg0;
        if (v1) g_logits[row1] = lg1;
        slog[warp * 2] = lg0;
        slog[warp * 2 + 1] = lg1;
    }
    __syncthreads();
    if (tid == 0) {
        float m = slog[0];
#pragma unroll
        for (int w = 1; w < ROWS_PER_BLK; w++) m = fmaxf(m, slog[w]);
        float s = 0.f;
#pragma unroll
        for (int w = 0; w < ROWS_PER_BLK; w++) s += expf(slog[w] - m);
        g_pmax[blockIdx.x] = m;
        g_psum[blockIdx.x] = s;
    }
}

// K67: global logsumexp reduce (redundant per block) + output write.
__global__ __launch_bounds__(256) void k67_write(float* __restrict__ out) {
    cudaGridDependencySynchronize();
    __shared__ float sm[256], ss[256];
    int tid = threadIdx.x;
    float m = -INFINITY, s = 0.f;
    for (int b = tid; b < NB5; b += 256)
        lse_merge(m, s, g_pmax[b], g_psum[b]);
    sm[tid] = m; ss[tid] = s;
    __syncthreads();
#pragma unroll
    for (int o = 128; o; o >>= 1) {
        if (tid < o) lse_merge(sm[tid], ss[tid], sm[tid + o], ss[tid + o]);
        __syncthreads();
    }
    __shared__ float shift;
    if (tid == 0) shift = sm[0] + logf(ss[0]);
    __syncthreads();
    int v = blockIdx.x * 256 + tid;
    if (v < Vdim) out[v] = g_logits[v] - shift;
}

static inline void launch_pdl(void* func, dim3 grid, dim3 block, void** args) {
    cudaLaunchAttribute attr[1];
    attr[0].id = cudaLaunchAttributeProgrammaticStreamSerialization;
    attr[0].val.programmaticStreamSerializationAllowed = 1;
    cudaLaunchConfig_t cfg = {};
    cfg.gridDim = grid;
    cfg.blockDim = block;
    cfg.dynamicSmemBytes = 0;
    cfg.stream = 0;
    cfg.attrs = attr;
    cfg.numAttrs = 1;
    cudaLaunchKernelExC(&cfg, func, args);
}

extern "C" void kernel_launch(void* const* d_in, const int* in_sizes, int n_in,
                              void* d_out, int out_size) {
    const int*   inp    = (const int*)  d_in[0];
    const float* hidden = (const float*)d_in[1];
    const float* enc    = (const float*)d_in[2];
    const float* emb    = (const float*)d_in[3];
    const float* attn_W = (const float*)d_in[4];
    const float* attn_b = (const float*)d_in[5];
    const float* comb_W = (const float*)d_in[6];
    const float* comb_b = (const float*)d_in[7];
    const float* gruwih = (const float*)d_in[8];
    const float* gruwhh = (const float*)d_in[9];
    const float* grubih = (const float*)d_in[10];
    const float* grubhh = (const float*)d_in[11];
    const float* out_W  = (const float*)d_in[12];
    const float* out_b  = (const float*)d_in[13];
    float* out = (float*)d_out;

    {   // independent gh half of the GRU — starts immediately
        void* args[] = { (void*)&hidden, (void*)&gruwhh, (void*)&grubhh };
        launch_pdl((void*)k0_gruh, dim3(Hdim), dim3(256), args);
    }
    {   // attention — also independent, overlaps k0 via PDL
        void* args[] = { (void*)&inp, (void*)&hidden, (void*)&enc, (void*)&emb,
                         (void*)&attn_W, (void*)&attn_b, (void*)&out, (void*)&out_size };
        launch_pdl((void*)k1_attn, dim3(1), dim3(1024), args);
    }
    {
        void* args[] = { (void*)&comb_W, (void*)&comb_b };
        launch_pdl((void*)k2_comb, dim3(Hdim), dim3(512), args);
    }
    {
        void* args[] = { (void*)&hidden, (void*)&gruwih, (void*)&grubih,
                         (void*)&out, (void*)&out_size };
        launch_pdl((void*)k3_grui, dim3(Hdim), dim3(256), args);
    }
    {
        void* args[] = { (void*)&out_W, (void*)&out_b };
        launch_pdl((void*)k5_logits, dim3(NB5), dim3(512), args);
    }
    {
        void* args[] = { (void*)&out };
        launch_pdl((void*)k67_write, dim3(NB7), dim3(256), args);
    }
}